// round 12
// baseline (speedup 1.0000x reference)
#include <cuda_runtime.h>
#include <cuda_bf16.h>
#include <math.h>

// ---------------- problem constants ----------------
#define Bq   2
#define Lq   2048
#define Dq   1024
#define Kq   32
#define Mq   4
#define Aq   4
#define Hq   32          // D / K
#define CKq  4
#define TOTq (2 * Dq + Kq)   // 2080
#define BLq  (Bq * Lq)       // 4096
#define HMq  (Hq * Mq)       // 128
#define C2q  (2 * HMq)       // 256 channels (re + im)
#define ROWSq (BLq * Kq)     // 131072 (b,l,k) rows
#define NCH  64              // chunks along L
#define CHq  (Lq / NCH)      // 32 steps per chunk

// ------------- scratch: EXACTLY the R7 (passing) static set -------------
__device__ float g_z[(size_t)BLq * TOTq];          // in_proj output; later hosts w2 bf16 split
__device__ float g_xv[(size_t)BLq * Dq];           // x_val (post conv)
__device__ float g_gate[(size_t)BLq * Dq];         // silu gate
__device__ float g_pw[(size_t)BLq * Kq];           // p * time_weight
__device__ float g_reim[(size_t)ROWSq * C2q];      // scan prefixes; hosts x/w1 bf16 splits pre-scan
__device__ float g_den[(size_t)ROWSq];
__device__ float g_csum[(size_t)Bq * Kq * NCH * C2q];
__device__ float g_dsum[(size_t)Bq * Kq * NCH];
__device__ float g_wn[C2q * Hq];                   // norm_scale-folded [W_re;W_im]
__device__ float g_yg[(size_t)BLq * Dq];           // hosts yg bf16 hi/lo

// ================= helpers =================
__device__ __forceinline__ unsigned smem_addr_u32(const void* p) {
    unsigned a;
    asm("{ .reg .u64 t; cvta.to.shared.u64 t, %1; cvt.u32.u64 %0, t; }"
        : "=r"(a) : "l"(p));
    return a;
}
__device__ __forceinline__ void ldmat4(unsigned& r0, unsigned& r1,
                                       unsigned& r2, unsigned& r3, unsigned a) {
    asm volatile("ldmatrix.sync.aligned.m8n8.x4.shared.b16 {%0,%1,%2,%3}, [%4];"
        : "=r"(r0), "=r"(r1), "=r"(r2), "=r"(r3) : "r"(a));
}
__device__ __forceinline__ void ldmat4t(unsigned& r0, unsigned& r1,
                                        unsigned& r2, unsigned& r3, unsigned a) {
    asm volatile("ldmatrix.sync.aligned.m8n8.x4.trans.shared.b16 {%0,%1,%2,%3}, [%4];"
        : "=r"(r0), "=r"(r1), "=r"(r2), "=r"(r3) : "r"(a));
}
__device__ __forceinline__ void mma16816(float* d, const unsigned* a, const unsigned* b) {
    asm volatile(
        "mma.sync.aligned.m16n8k16.row.col.f32.bf16.bf16.f32 "
        "{%0,%1,%2,%3}, {%4,%5,%6,%7}, {%8,%9}, {%0,%1,%2,%3};"
        : "+f"(d[0]), "+f"(d[1]), "+f"(d[2]), "+f"(d[3])
        : "r"(a[0]), "r"(a[1]), "r"(a[2]), "r"(a[3]), "r"(b[0]), "r"(b[1]));
}

// ---------------- fp32 -> bf16 hi/lo split prepass (pure scalar) ----------
// which: 0 = x -> g_reim[0..), 1 = w1 -> g_reim after x, 2 = w2 -> g_z.
// No local arrays, no references-to-locals: zero local-memory surface.
__global__ void split_kernel(const float* __restrict__ src, int which, int n)
{
    const int i = blockIdx.x * blockDim.x + threadIdx.x;
    if (i >= n) return;
    unsigned short* hi;
    unsigned short* lo;
    if (which == 0) {
        hi = (unsigned short*)g_reim;
        lo = hi + (size_t)BLq * Dq;
    } else if (which == 1) {
        hi = (unsigned short*)g_reim + 2 * (size_t)BLq * Dq;
        lo = hi + (size_t)Dq * TOTq;
    } else {
        hi = (unsigned short*)g_z;
        lo = hi + (size_t)Dq * Dq;
    }
    const float v = src[i];
    const unsigned b = __float_as_uint(v);
    const unsigned r = b + 0x7FFFu + ((b >> 16) & 1u);   // rn-even to bf16
    const unsigned short h = (unsigned short)(r >> 16);
    const float hf = __uint_as_float((unsigned)h << 16);
    const float lf = v - hf;
    const unsigned lb = __float_as_uint(lf);
    const unsigned lr = lb + 0x7FFFu + ((lb >> 16) & 1u);
    hi[i] = h;
    lo[i] = (unsigned short)(lr >> 16);
}

// ================= bf16-split tensor-core GEMM (pre-split inputs) ==========
// C = (Ah+Al)*(Bh+Bl) keeping hh+hl+lh, fp32 accumulate. R7-proven skeleton:
// 128x128x32 block, 8 warps, double-buffered SMEM, register prefetch.
#define APADg 40     // A k-stride in bf16 elems (80B row, ldmatrix conflict-free)
#define BPADg 136    // B n-stride in bf16 elems (272B row)
#define OAh 0
#define OAl (128 * APADg)                 // 5120
#define OBh (OAl + 128 * APADg)           // 10240
#define OBl (OBh + 32 * BPADg)            // 14592
#define STg (OBl + 32 * BPADg)            // 18944 elems per stage
#define GEMM_SMEM_BYTES (2 * STg * 2)     // 75776 bytes

__device__ __forceinline__ void hgemm_body(
    const __nv_bfloat16* __restrict__ Ah, const __nv_bfloat16* __restrict__ Al,
    const __nv_bfloat16* __restrict__ Bh, const __nv_bfloat16* __restrict__ Bl,
    float* __restrict__ C, int Nc, int Kd)
{
    extern __shared__ __align__(16) __nv_bfloat16 sm[];
    const unsigned sbase = smem_addr_u32(sm);

    const int tid  = threadIdx.x;
    const int lane = tid & 31;
    const int warp = tid >> 5;
    const int wm = (warp >> 2) * 64;
    const int wn = (warp & 3) * 32;
    const int bm0 = blockIdx.y * 128;
    const int bn0 = blockIdx.x * 128;

    float acc[4][4][4];
#pragma unroll
    for (int i = 0; i < 4; ++i)
#pragma unroll
        for (int j = 0; j < 4; ++j)
#pragma unroll
            for (int r = 0; r < 4; ++r) acc[i][j][r] = 0.f;

    int aRow[4], aC4[4], bRow[4], bC4[4];
#pragma unroll
    for (int i = 0; i < 4; ++i) {
        const int lin = i * 256 + tid;
        aRow[i] = lin >> 3;  aC4[i] = (lin & 7) * 4;
        bRow[i] = lin >> 5;  bC4[i] = (lin & 31) * 4;
    }

    const int nKT = Kd >> 5;
    uint2 ha[4], la[4], hb[4], lb[4];
    const uint2 z2 = make_uint2(0u, 0u);

    // preload tile 0
#pragma unroll
    for (int i = 0; i < 4; ++i) {
        const size_t ga = (size_t)(bm0 + aRow[i]) * Kd + aC4[i];
        ha[i] = *reinterpret_cast<const uint2*>(Ah + ga);
        la[i] = *reinterpret_cast<const uint2*>(Al + ga);
        const int gbc = bn0 + bC4[i];
        hb[i] = z2; lb[i] = z2;
        if (gbc < Nc) {   // Nc % 4 == 0 -> whole-chunk predicate
            const size_t gb = (size_t)bRow[i] * Nc + gbc;
            hb[i] = *reinterpret_cast<const uint2*>(Bh + gb);
            lb[i] = *reinterpret_cast<const uint2*>(Bl + gb);
        }
    }
#pragma unroll
    for (int i = 0; i < 4; ++i) {
        *reinterpret_cast<uint2*>(&sm[OAh + aRow[i] * APADg + aC4[i]]) = ha[i];
        *reinterpret_cast<uint2*>(&sm[OAl + aRow[i] * APADg + aC4[i]]) = la[i];
        *reinterpret_cast<uint2*>(&sm[OBh + bRow[i] * BPADg + bC4[i]]) = hb[i];
        *reinterpret_cast<uint2*>(&sm[OBl + bRow[i] * BPADg + bC4[i]]) = lb[i];
    }
    __syncthreads();

    int st = 0;
    for (int kt = 0; kt < nKT; ++kt) {
        const bool more = (kt + 1 < nKT);
        if (more) {
            const int k0 = (kt + 1) * 32;
#pragma unroll
            for (int i = 0; i < 4; ++i) {
                const size_t ga = (size_t)(bm0 + aRow[i]) * Kd + k0 + aC4[i];
                ha[i] = *reinterpret_cast<const uint2*>(Ah + ga);
                la[i] = *reinterpret_cast<const uint2*>(Al + ga);
                const int gbc = bn0 + bC4[i];
                hb[i] = z2; lb[i] = z2;
                if (gbc < Nc) {
                    const size_t gb = (size_t)(k0 + bRow[i]) * Nc + gbc;
                    hb[i] = *reinterpret_cast<const uint2*>(Bh + gb);
                    lb[i] = *reinterpret_cast<const uint2*>(Bl + gb);
                }
            }
        }

#pragma unroll
        for (int kk = 0; kk < 32; kk += 16) {
            unsigned afh[4][4], afl[4][4];
            const int arowL = (lane & 7) + ((lane >> 3) & 1) * 8;
            const int acolL = kk + (lane >> 4) * 8;
#pragma unroll
            for (int i = 0; i < 4; ++i) {
                const unsigned ad = sbase +
                    (unsigned)(st + OAh + (wm + i * 16 + arowL) * APADg + acolL) * 2u;
                ldmat4(afh[i][0], afh[i][1], afh[i][2], afh[i][3], ad);
                ldmat4(afl[i][0], afl[i][1], afl[i][2], afl[i][3],
                       ad + (unsigned)(OAl - OAh) * 2u);
            }
            unsigned bfh[4][2], bfl[4][2];
            const int krow = kk + (lane & 7) + ((lane >> 3) & 1) * 8;
#pragma unroll
            for (int jj = 0; jj < 32; jj += 16) {
                const int ncol = wn + jj + (lane >> 4) * 8;
                const unsigned bd = sbase +
                    (unsigned)(st + OBh + krow * BPADg + ncol) * 2u;
                unsigned r0, r1, r2, r3;
                ldmat4t(r0, r1, r2, r3, bd);
                bfh[jj / 8 + 0][0] = r0; bfh[jj / 8 + 0][1] = r1;
                bfh[jj / 8 + 1][0] = r2; bfh[jj / 8 + 1][1] = r3;
                ldmat4t(r0, r1, r2, r3, bd + (unsigned)(OBl - OBh) * 2u);
                bfl[jj / 8 + 0][0] = r0; bfl[jj / 8 + 0][1] = r1;
                bfl[jj / 8 + 1][0] = r2; bfl[jj / 8 + 1][1] = r3;
            }
#pragma unroll
            for (int i = 0; i < 4; ++i)
#pragma unroll
                for (int j = 0; j < 4; ++j) {
                    mma16816(acc[i][j], afh[i], bfh[j]);   // hi*hi
                    mma16816(acc[i][j], afh[i], bfl[j]);   // hi*lo
                    mma16816(acc[i][j], afl[i], bfh[j]);   // lo*hi
                }
        }

        if (more) {
            const int ns = st ^ STg;
#pragma unroll
            for (int i = 0; i < 4; ++i) {
                *reinterpret_cast<uint2*>(&sm[ns + OAh + aRow[i] * APADg + aC4[i]]) = ha[i];
                *reinterpret_cast<uint2*>(&sm[ns + OAl + aRow[i] * APADg + aC4[i]]) = la[i];
                *reinterpret_cast<uint2*>(&sm[ns + OBh + bRow[i] * BPADg + bC4[i]]) = hb[i];
                *reinterpret_cast<uint2*>(&sm[ns + OBl + bRow[i] * BPADg + bC4[i]]) = lb[i];
            }
            __syncthreads();
            st = ns;
        }
    }

    const int g = lane >> 2;
    const int t2 = (lane & 3) * 2;
#pragma unroll
    for (int i = 0; i < 4; ++i) {
        const int row = bm0 + wm + i * 16 + g;
#pragma unroll
        for (int j = 0; j < 4; ++j) {
            const int col = bn0 + wn + j * 8 + t2;
            if (col < Nc) {
                *reinterpret_cast<float2*>(&C[(size_t)row * Nc + col]) =
                    make_float2(acc[i][j][0], acc[i][j][1]);
                *reinterpret_cast<float2*>(&C[(size_t)(row + 8) * Nc + col]) =
                    make_float2(acc[i][j][2], acc[i][j][3]);
            }
        }
    }
}

__global__ __launch_bounds__(256) void gemm_in()
{
    const __nv_bfloat16* xh  = (const __nv_bfloat16*)g_reim;
    const __nv_bfloat16* xl  = xh + (size_t)BLq * Dq;
    const __nv_bfloat16* w1h = xl + (size_t)BLq * Dq;
    const __nv_bfloat16* w1l = w1h + (size_t)Dq * TOTq;
    hgemm_body(xh, xl, w1h, w1l, g_z, TOTq, Dq);
}

__global__ __launch_bounds__(256) void gemm_out(float* __restrict__ out)
{
    const __nv_bfloat16* ygh = (const __nv_bfloat16*)g_yg;
    const __nv_bfloat16* ygl = ygh + (size_t)BLq * Dq;
    const __nv_bfloat16* w2h = (const __nv_bfloat16*)g_z;
    const __nv_bfloat16* w2l = w2h + (size_t)Dq * Dq;
    hgemm_body(ygh, ygl, w2h, w2l, out, Dq, Dq);
}

// ---------------- depthwise causal conv + pointwise classify ----------------
__global__ void conv_kernel(
    const float* __restrict__ cw, const float* __restrict__ cb,
    const float* __restrict__ dslopes, const float* __restrict__ aslopes,
    const float* __restrict__ sscale)
{
    const size_t i = (size_t)blockIdx.x * blockDim.x + threadIdx.x;
    if (i >= (size_t)BLq * TOTq) return;
    const int c = (int)(i % TOTq);
    const size_t bl = i / TOTq;
    const int l = (int)(bl % Lq);

    float acc = cb[c];
#pragma unroll
    for (int j = 0; j < CKq; ++j) {
        const int ls = l + j - (CKq - 1);
        if (ls >= 0)
            acc = fmaf(g_z[(bl - l + ls) * TOTq + c], cw[j * TOTq + c], acc);
    }

    if (c < Dq) {
        g_xv[bl * Dq + c] = acc;
    } else if (c < 2 * Dq) {
        g_gate[bl * Dq + (c - Dq)] = acc / (1.f + __expf(-acc));
    } else {
        const int k = c - 2 * Dq;
        float s = sscale[k] * acc;
        s = fminf(fmaxf(s, -20.f), 20.f);
        const float p = __expf(s);
        float sl, tw;
        if (k < Kq - Aq) {
            sl = log1pf(expf(dslopes[k]));                 // softplus
            tw = __expf(-sl * (float)(Lq - 1 - l));
        } else {
            sl = log1pf(expf(aslopes[k - (Kq - Aq)]));
            tw = __expf(-sl * (float)l);
        }
        g_pw[bl * Kq + k] = p * tw;
    }
}

// ---------------- fold norm_scale into [W_re; W_im] ----------------
__global__ void prep_wn(const float* __restrict__ ns,
                        const float* __restrict__ Wre,
                        const float* __restrict__ Wim)
{
    const int i = blockIdx.x * blockDim.x + threadIdx.x;
    if (i >= C2q * Hq) return;
    const int c = i / Hq, hh = i % Hq;
    const float w = (c < HMq) ? Wre[c * Hq + hh] : Wim[(c - HMq) * Hq + hh];
    g_wn[i] = ns[c] * w;
}

// ---------------- pass 1: per-chunk compute + local cumsum ------------------
__global__ __launch_bounds__(256) void scan_part(
    const float* __restrict__ theta, const float* __restrict__ dlog)
{
    const int bid   = blockIdx.x;            // bk * NCH + chunk
    const int bk    = bid >> 6;              // NCH == 64
    const int chunk = bid & (NCH - 1);
    const int b = bk >> 5, k = bk & (Kq - 1);
    const int c = threadIdx.x;
    const int c2 = c & (HMq - 1);
    const int h = c2 >> 2;
    const int m = c2 & (Mq - 1);
    const bool isIm = (c >= HMq);

    const float th = theta[(k * Hq + h) * Mq + m];

    const float d0 = dlog[0], d1 = dlog[1], d2 = dlog[2];
    const float mx = fmaxf(d0, fmaxf(d1, d2));
    const float e0 = __expf(d0 - mx), e1 = __expf(d1 - mx), e2 = __expf(d2 - mx);
    const float inv = 1.f / (e0 + e1 + e2);
    const float w0 = e0 * inv, w1 = e1 * inv, w2 = e2 * inv;

    const int l0 = chunk * CHq;
    const float* xp = g_xv + ((size_t)b * Lq + l0) * Dq + k * Hq + h;
    const float* pp = g_pw + ((size_t)b * Lq + l0) * Kq + k;
    float* op = g_reim + (((size_t)b * Lq + l0) * Kq + k) * C2q + c;
    float* dp = g_den + ((size_t)b * Lq + l0) * Kq + k;

    float acc = 0.f, dacc = 0.f;
#pragma unroll 4
    for (int s = 0; s < CHq; ++s) {
        const float x = *xp;
        const float p = *pp;
        float sv, cv;
        __sincosf(x * th, &sv, &cv);
        const float poly = w0 + x * (w1 - w2 * x);
        const float v = poly * (isIm ? sv : cv);
        acc = fmaf(p, v, acc);
        dacc += p;
        *op = acc;
        if (c == 0) *dp = dacc;
        xp += Dq;
        pp += Kq;
        op += Kq * C2q;
        dp += Kq;
    }
    g_csum[(size_t)bid * C2q + c] = acc;
    if (c == 0) g_dsum[bid] = dacc;
}

// ---------------- pass 2: exclusive scan of chunk sums ----------------------
__global__ __launch_bounds__(256) void scan_fix()
{
    const int bk = blockIdx.x;
    const int c = threadIdx.x;
    float run = 0.f;
#pragma unroll 4
    for (int ch = 0; ch < NCH; ++ch) {
        const size_t idx = ((size_t)bk * NCH + ch) * C2q + c;
        const float t = g_csum[idx];
        g_csum[idx] = run;
        run += t;
    }
    if (c == 0) {
        float dr = 0.f;
        for (int ch = 0; ch < NCH; ++ch) {
            const int idx = bk * NCH + ch;
            const float t = g_dsum[idx];
            g_dsum[idx] = dr;
            dr += t;
        }
    }
}

// -------- RMS-norm + 256->32 projection + gate; scalar bf16 hi/lo tail -----
__global__ __launch_bounds__(256) void proj_kernel()
{
    __shared__ float sWn[C2q * Hq];          // 32 KB
    __shared__ float rowbuf[8][C2q];         // 8 KB

    for (int i = threadIdx.x; i < C2q * Hq; i += 256) sWn[i] = g_wn[i];
    __syncthreads();

    const int warp = threadIdx.x >> 5;
    const int lane = threadIdx.x & 31;
    const size_t row = (size_t)blockIdx.x * 8 + warp;   // < ROWSq exactly

    const size_t bl = row >> 5;              // K == 32
    const int k = (int)(row & 31);
    const int b = (int)(bl >> 11);           // L == 2048
    const int l = (int)(bl & (Lq - 1));
    const int chunk = l >> 5;                // CHq == 32
    const size_t obase = (((size_t)(b * Kq + k)) * NCH + chunk) * C2q;

    const float* rp = g_reim + row * C2q;
    const float* cp = g_csum + obase;
    float ss = 0.f;
#pragma unroll
    for (int j = 0; j < 8; ++j) {
        const float v = rp[lane + 32 * j] + cp[lane + 32 * j];
        ss = fmaf(v, v, ss);
        rowbuf[warp][lane + 32 * j] = v;
    }
#pragma unroll
    for (int o = 16; o; o >>= 1) ss += __shfl_xor_sync(0xFFFFFFFFu, ss, o);

    const float den = g_den[row] + g_dsum[(b * Kq + k) * NCH + chunk];
    const float invd = 1.f / fmaxf(den, 1e-4f);
    const float ms = ss * invd * invd * (1.f / (float)C2q);
    const float scale = invd * rsqrtf(ms + 1e-5f);
    __syncwarp();

    float acc = 0.f;
#pragma unroll 4
    for (int cc = 0; cc < C2q; ++cc)
        acc = fmaf(rowbuf[warp][cc], sWn[cc * Hq + lane], acc);

    const size_t oidx = bl * Dq + k * Hq + lane;
    const float val = acc * scale * g_gate[oidx];
    // scalar bf16 hi/lo split (rn-even via bit trick; no locals addressed)
    const unsigned vb = __float_as_uint(val);
    const unsigned vr = vb + 0x7FFFu + ((vb >> 16) & 1u);
    const unsigned short hv = (unsigned short)(vr >> 16);
    const float hf = __uint_as_float((unsigned)hv << 16);
    const float lf = val - hf;
    const unsigned lb2 = __float_as_uint(lf);
    const unsigned lr2 = lb2 + 0x7FFFu + ((lb2 >> 16) & 1u);
    ((unsigned short*)g_yg)[oidx] = hv;
    ((unsigned short*)g_yg)[(size_t)BLq * Dq + oidx] = (unsigned short)(lr2 >> 16);
}

// ---------------- launch ----------------
extern "C" void kernel_launch(void* const* d_in, const int* in_sizes, int n_in,
                              void* d_out, int out_size)
{
    const float* x        = (const float*)d_in[0];
    const float* in_proj  = (const float*)d_in[1];
    const float* conv_w   = (const float*)d_in[2];
    const float* conv_b   = (const float*)d_in[3];
    const float* theta    = (const float*)d_in[4];
    const float* decay    = (const float*)d_in[5];
    const float* anchor   = (const float*)d_in[6];
    const float* sscale   = (const float*)d_in[7];
    const float* dlog     = (const float*)d_in[8];
    const float* nscale   = (const float*)d_in[9];
    const float* Wre      = (const float*)d_in[10];
    const float* Wim      = (const float*)d_in[11];
    const float* outw     = (const float*)d_in[12];
    float* out = (float*)d_out;

    cudaFuncSetAttribute(gemm_in, cudaFuncAttributeMaxDynamicSharedMemorySize,
                         GEMM_SMEM_BYTES);
    cudaFuncSetAttribute(gemm_out, cudaFuncAttributeMaxDynamicSharedMemorySize,
                         GEMM_SMEM_BYTES);

    // 0) pre-split x and w1 into bf16 hi/lo (carved into g_reim, dead until scan)
    {
        const int nx = BLq * Dq;
        split_kernel<<<(nx + 255) / 256, 256>>>(x, 0, nx);
        const int n1 = Dq * TOTq;
        split_kernel<<<(n1 + 255) / 256, 256>>>(in_proj, 1, n1);
    }
    // 1) z = x @ in_proj_w     (4096 x 2080 x 1024)  [tensor cores]
    {
        dim3 grid((TOTq + 127) / 128, BLq / 128);
        gemm_in<<<grid, 256, GEMM_SMEM_BYTES>>>();
    }
    // 2) depthwise causal conv + silu gate + p*time_weight
    {
        const long total = (long)BLq * TOTq;
        conv_kernel<<<(int)((total + 255) / 256), 256>>>(conv_w, conv_b, decay, anchor, sscale);
    }
    // 2.5) g_z now dead -> host w2 bf16 split there
    {
        const int n2 = Dq * Dq;
        split_kernel<<<(n2 + 255) / 256, 256>>>(outw, 2, n2);
    }
    // 3) fold norm_scale into W
    prep_wn<<<(C2q * Hq + 255) / 256, 256>>>(nscale, Wre, Wim);
    // 4) chunked parallel cumsum (overwrites the x/w1 split regions — dead)
    scan_part<<<Bq * Kq * NCH, 256>>>(theta, dlog);
    scan_fix<<<Bq * Kq, 256>>>();
    // 5) RMS norm + head projection + gate -> bf16 hi/lo yg (into g_yg)
    proj_kernel<<<ROWSq / 8, 256>>>();
    // 6) out = yg @ out_proj_w  (4096 x 1024 x 1024)  [tensor cores]
    {
        dim3 grid((Dq + 127) / 128, BLq / 128);
        gemm_out<<<grid, 256, GEMM_SMEM_BYTES>>>(out);
    }
}

// round 14
// speedup vs baseline: 1.1301x; 1.1301x over previous
#include <cuda_runtime.h>
#include <cuda_bf16.h>
#include <cuda_fp16.h>
#include <math.h>

// ---------------- problem constants ----------------
#define Bq   2
#define Lq   2048
#define Dq   1024
#define Kq   32
#define Mq   4
#define Aq   4
#define Hq   32          // D / K
#define CKq  4
#define TOTq (2 * Dq + Kq)   // 2080
#define BLq  (Bq * Lq)       // 4096
#define HMq  (Hq * Mq)       // 128
#define C2q  (2 * HMq)       // 256 channels (re + im)
#define ROWSq (BLq * Kq)     // 131072 (b,l,k) rows
#define NCH  64              // chunks along L
#define CHq  (Lq / NCH)      // 32 steps per chunk

// ------------- scratch: EXACTLY the R7/R12 (passing) static set -------------
__device__ float g_z[(size_t)BLq * TOTq];          // in_proj output; later hosts w2 fp16 split
__device__ float g_xv[(size_t)BLq * Dq];           // x_val (post conv)
__device__ float g_gate[(size_t)BLq * Dq];         // silu gate
__device__ float g_pw[(size_t)BLq * Kq];           // p * time_weight
__device__ float g_reim[(size_t)ROWSq * C2q];      // scan prefixes; hosts x/w1 fp16 splits pre-scan
__device__ float g_den[(size_t)ROWSq];
__device__ float g_csum[(size_t)Bq * Kq * NCH * C2q];
__device__ float g_dsum[(size_t)Bq * Kq * NCH];
__device__ float g_wn[C2q * Hq];                   // norm_scale-folded [W_re;W_im]
__device__ float g_yg[(size_t)BLq * Dq];           // hosts yg fp16

// ================= helpers =================
__device__ __forceinline__ unsigned smem_addr_u32(const void* p) {
    unsigned a;
    asm("{ .reg .u64 t; cvta.to.shared.u64 t, %1; cvt.u32.u64 %0, t; }"
        : "=r"(a) : "l"(p));
    return a;
}
__device__ __forceinline__ void ldmat4(unsigned& r0, unsigned& r1,
                                       unsigned& r2, unsigned& r3, unsigned a) {
    asm volatile("ldmatrix.sync.aligned.m8n8.x4.shared.b16 {%0,%1,%2,%3}, [%4];"
        : "=r"(r0), "=r"(r1), "=r"(r2), "=r"(r3) : "r"(a));
}
__device__ __forceinline__ void ldmat4t(unsigned& r0, unsigned& r1,
                                        unsigned& r2, unsigned& r3, unsigned a) {
    asm volatile("ldmatrix.sync.aligned.m8n8.x4.trans.shared.b16 {%0,%1,%2,%3}, [%4];"
        : "=r"(r0), "=r"(r1), "=r"(r2), "=r"(r3) : "r"(a));
}
__device__ __forceinline__ void mmaf16(float* d, const unsigned* a, const unsigned* b) {
    asm volatile(
        "mma.sync.aligned.m16n8k16.row.col.f32.f16.f16.f32 "
        "{%0,%1,%2,%3}, {%4,%5,%6,%7}, {%8,%9}, {%0,%1,%2,%3};"
        : "+f"(d[0]), "+f"(d[1]), "+f"(d[2]), "+f"(d[3])
        : "r"(a[0]), "r"(a[1]), "r"(a[2]), "r"(a[3]), "r"(b[0]), "r"(b[1]));
}

// ------------- fp32 -> fp16 splits (pure scalar, no locals addressed) -------
// x (and yg via proj tail): single fp16. Weights: fp16 hi/lo, pre-scaled x1024
// so lo residuals stay in fp16 normal range; GEMM epilogue multiplies 1/1024.
__global__ void split_x_f16(const float* __restrict__ src, int n)
{
    const int i = blockIdx.x * blockDim.x + threadIdx.x;
    if (i >= n) return;
    ((unsigned short*)g_reim)[i] = __half_as_ushort(__float2half_rn(src[i]));
}
__global__ void split_w_f16(const float* __restrict__ src, int which, int n)
{
    const int i = blockIdx.x * blockDim.x + threadIdx.x;
    if (i >= n) return;
    unsigned short* hi;
    unsigned short* lo;
    if (which == 1) {
        hi = (unsigned short*)g_reim + (size_t)BLq * Dq;
        lo = hi + (size_t)Dq * TOTq;
    } else {
        hi = (unsigned short*)g_z;
        lo = hi + (size_t)Dq * Dq;
    }
    const float v = src[i] * 1024.f;
    const __half h = __float2half_rn(v);
    hi[i] = __half_as_ushort(h);
    lo[i] = __half_as_ushort(__float2half_rn(v - __half2float(h)));
}

// ========== asymmetric fp16 tensor-core GEMM: C = A * (Bh+Bl) / 1024 =======
// A single fp16 [M,K]; B fp16 hi/lo [K,N] (pre-scaled x1024). 2 mma per k16.
// R12-proven skeleton: 128x128x32 block, 8 warps, double-buffered SMEM,
// register prefetch, fp32 accumulate, epilogue scales by 1/1024.
#define APADg 40     // A k-stride in fp16 elems (80B row, ldmatrix conflict-free)
#define BPADg 136    // B n-stride in fp16 elems (272B row)
#define OAg  0
#define OBh (128 * APADg)                 // 5120
#define OBl (OBh + 32 * BPADg)            // 9472
#define STg (OBl + 32 * BPADg)            // 13824 elems per stage
#define GEMM_SMEM_BYTES (2 * STg * 2)     // 55296 bytes

__device__ __forceinline__ void hgemm_body(
    const unsigned short* __restrict__ Ah,
    const unsigned short* __restrict__ Bh, const unsigned short* __restrict__ Bl,
    float* __restrict__ C, int Nc, int Kd)
{
    extern __shared__ __align__(16) unsigned short sm[];
    const unsigned sbase = smem_addr_u32(sm);

    const int tid  = threadIdx.x;
    const int lane = tid & 31;
    const int warp = tid >> 5;
    const int wm = (warp >> 2) * 64;
    const int wn = (warp & 3) * 32;
    const int bm0 = blockIdx.y * 128;
    const int bn0 = blockIdx.x * 128;

    float acc[4][4][4];
#pragma unroll
    for (int i = 0; i < 4; ++i)
#pragma unroll
        for (int j = 0; j < 4; ++j)
#pragma unroll
            for (int r = 0; r < 4; ++r) acc[i][j][r] = 0.f;

    int aRow[4], aC4[4], bRow[4], bC4[4];
#pragma unroll
    for (int i = 0; i < 4; ++i) {
        const int lin = i * 256 + tid;
        aRow[i] = lin >> 3;  aC4[i] = (lin & 7) * 4;
        bRow[i] = lin >> 5;  bC4[i] = (lin & 31) * 4;
    }

    const int nKT = Kd >> 5;
    uint2 ha[4], hb[4], lb[4];
    const uint2 z2 = make_uint2(0u, 0u);

    // preload tile 0
#pragma unroll
    for (int i = 0; i < 4; ++i) {
        ha[i] = *reinterpret_cast<const uint2*>(Ah + (size_t)(bm0 + aRow[i]) * Kd + aC4[i]);
        const int gbc = bn0 + bC4[i];
        hb[i] = z2; lb[i] = z2;
        if (gbc < Nc) {   // Nc % 4 == 0 -> whole-chunk predicate
            const size_t gb = (size_t)bRow[i] * Nc + gbc;
            hb[i] = *reinterpret_cast<const uint2*>(Bh + gb);
            lb[i] = *reinterpret_cast<const uint2*>(Bl + gb);
        }
    }
#pragma unroll
    for (int i = 0; i < 4; ++i) {
        *reinterpret_cast<uint2*>(&sm[OAg + aRow[i] * APADg + aC4[i]]) = ha[i];
        *reinterpret_cast<uint2*>(&sm[OBh + bRow[i] * BPADg + bC4[i]]) = hb[i];
        *reinterpret_cast<uint2*>(&sm[OBl + bRow[i] * BPADg + bC4[i]]) = lb[i];
    }
    __syncthreads();

    int st = 0;
    for (int kt = 0; kt < nKT; ++kt) {
        const bool more = (kt + 1 < nKT);
        if (more) {
            const int k0 = (kt + 1) * 32;
#pragma unroll
            for (int i = 0; i < 4; ++i) {
                ha[i] = *reinterpret_cast<const uint2*>(
                    Ah + (size_t)(bm0 + aRow[i]) * Kd + k0 + aC4[i]);
                const int gbc = bn0 + bC4[i];
                hb[i] = z2; lb[i] = z2;
                if (gbc < Nc) {
                    const size_t gb = (size_t)(k0 + bRow[i]) * Nc + gbc;
                    hb[i] = *reinterpret_cast<const uint2*>(Bh + gb);
                    lb[i] = *reinterpret_cast<const uint2*>(Bl + gb);
                }
            }
        }

#pragma unroll
        for (int kk = 0; kk < 32; kk += 16) {
            unsigned af[4][4];
            const int arowL = (lane & 7) + ((lane >> 3) & 1) * 8;
            const int acolL = kk + (lane >> 4) * 8;
#pragma unroll
            for (int i = 0; i < 4; ++i) {
                const unsigned ad = sbase +
                    (unsigned)(st + OAg + (wm + i * 16 + arowL) * APADg + acolL) * 2u;
                ldmat4(af[i][0], af[i][1], af[i][2], af[i][3], ad);
            }
            unsigned bfh[4][2], bfl[4][2];
            const int krow = kk + (lane & 7) + ((lane >> 3) & 1) * 8;
#pragma unroll
            for (int jj = 0; jj < 32; jj += 16) {
                const int ncol = wn + jj + (lane >> 4) * 8;
                const unsigned bd = sbase +
                    (unsigned)(st + OBh + krow * BPADg + ncol) * 2u;
                unsigned r0, r1, r2, r3;
                ldmat4t(r0, r1, r2, r3, bd);
                bfh[jj / 8 + 0][0] = r0; bfh[jj / 8 + 0][1] = r1;
                bfh[jj / 8 + 1][0] = r2; bfh[jj / 8 + 1][1] = r3;
                ldmat4t(r0, r1, r2, r3, bd + (unsigned)(OBl - OBh) * 2u);
                bfl[jj / 8 + 0][0] = r0; bfl[jj / 8 + 0][1] = r1;
                bfl[jj / 8 + 1][0] = r2; bfl[jj / 8 + 1][1] = r3;
            }
#pragma unroll
            for (int i = 0; i < 4; ++i)
#pragma unroll
                for (int j = 0; j < 4; ++j) {
                    mmaf16(acc[i][j], af[i], bfh[j]);   // A * B_hi
                    mmaf16(acc[i][j], af[i], bfl[j]);   // A * B_lo
                }
        }

        if (more) {
            const int ns = st ^ STg;
#pragma unroll
            for (int i = 0; i < 4; ++i) {
                *reinterpret_cast<uint2*>(&sm[ns + OAg + aRow[i] * APADg + aC4[i]]) = ha[i];
                *reinterpret_cast<uint2*>(&sm[ns + OBh + bRow[i] * BPADg + bC4[i]]) = hb[i];
                *reinterpret_cast<uint2*>(&sm[ns + OBl + bRow[i] * BPADg + bC4[i]]) = lb[i];
            }
            __syncthreads();
            st = ns;
        }
    }

    // epilogue: undo the x1024 B pre-scale
    const float inv1024 = 1.f / 1024.f;
    const int g = lane >> 2;
    const int t2 = (lane & 3) * 2;
#pragma unroll
    for (int i = 0; i < 4; ++i) {
        const int row = bm0 + wm + i * 16 + g;
#pragma unroll
        for (int j = 0; j < 4; ++j) {
            const int col = bn0 + wn + j * 8 + t2;
            if (col < Nc) {
                *reinterpret_cast<float2*>(&C[(size_t)row * Nc + col]) =
                    make_float2(acc[i][j][0] * inv1024, acc[i][j][1] * inv1024);
                *reinterpret_cast<float2*>(&C[(size_t)(row + 8) * Nc + col]) =
                    make_float2(acc[i][j][2] * inv1024, acc[i][j][3] * inv1024);
            }
        }
    }
}

__global__ __launch_bounds__(256) void gemm_in()
{
    const unsigned short* xh  = (const unsigned short*)g_reim;
    const unsigned short* w1h = xh + (size_t)BLq * Dq;
    const unsigned short* w1l = w1h + (size_t)Dq * TOTq;
    hgemm_body(xh, w1h, w1l, g_z, TOTq, Dq);
}

__global__ __launch_bounds__(256) void gemm_out(float* __restrict__ out)
{
    const unsigned short* ygh = (const unsigned short*)g_yg;
    const unsigned short* w2h = (const unsigned short*)g_z;
    const unsigned short* w2l = w2h + (size_t)Dq * Dq;
    hgemm_body(ygh, w2h, w2l, out, Dq, Dq);
}

// ---------------- depthwise causal conv + pointwise classify ----------------
__global__ void conv_kernel(
    const float* __restrict__ cw, const float* __restrict__ cb,
    const float* __restrict__ dslopes, const float* __restrict__ aslopes,
    const float* __restrict__ sscale)
{
    const size_t i = (size_t)blockIdx.x * blockDim.x + threadIdx.x;
    if (i >= (size_t)BLq * TOTq) return;
    const int c = (int)(i % TOTq);
    const size_t bl = i / TOTq;
    const int l = (int)(bl % Lq);

    float acc = cb[c];
#pragma unroll
    for (int j = 0; j < CKq; ++j) {
        const int ls = l + j - (CKq - 1);
        if (ls >= 0)
            acc = fmaf(g_z[(bl - l + ls) * TOTq + c], cw[j * TOTq + c], acc);
    }

    if (c < Dq) {
        g_xv[bl * Dq + c] = acc;
    } else if (c < 2 * Dq) {
        g_gate[bl * Dq + (c - Dq)] = acc / (1.f + __expf(-acc));
    } else {
        const int k = c - 2 * Dq;
        float s = sscale[k] * acc;
        s = fminf(fmaxf(s, -20.f), 20.f);
        const float p = __expf(s);
        float sl, tw;
        if (k < Kq - Aq) {
            sl = log1pf(expf(dslopes[k]));                 // softplus
            tw = __expf(-sl * (float)(Lq - 1 - l));
        } else {
            sl = log1pf(expf(aslopes[k - (Kq - Aq)]));
            tw = __expf(-sl * (float)l);
        }
        g_pw[bl * Kq + k] = p * tw;
    }
}

// ---------------- fold norm_scale into [W_re; W_im] ----------------
__global__ void prep_wn(const float* __restrict__ ns,
                        const float* __restrict__ Wre,
                        const float* __restrict__ Wim)
{
    const int i = blockIdx.x * blockDim.x + threadIdx.x;
    if (i >= C2q * Hq) return;
    const int c = i / Hq, hh = i % Hq;
    const float w = (c < HMq) ? Wre[c * Hq + hh] : Wim[(c - HMq) * Hq + hh];
    g_wn[i] = ns[c] * w;
}

// ---------------- pass 1: per-chunk compute + local cumsum ------------------
__global__ __launch_bounds__(256) void scan_part(
    const float* __restrict__ theta, const float* __restrict__ dlog)
{
    const int bid   = blockIdx.x;            // bk * NCH + chunk
    const int bk    = bid >> 6;              // NCH == 64
    const int chunk = bid & (NCH - 1);
    const int b = bk >> 5, k = bk & (Kq - 1);
    const int c = threadIdx.x;
    const int c2 = c & (HMq - 1);
    const int h = c2 >> 2;
    const int m = c2 & (Mq - 1);
    const bool isIm = (c >= HMq);

    const float th = theta[(k * Hq + h) * Mq + m];

    const float d0 = dlog[0], d1 = dlog[1], d2 = dlog[2];
    const float mx = fmaxf(d0, fmaxf(d1, d2));
    const float e0 = __expf(d0 - mx), e1 = __expf(d1 - mx), e2 = __expf(d2 - mx);
    const float inv = 1.f / (e0 + e1 + e2);
    const float w0 = e0 * inv, w1 = e1 * inv, w2 = e2 * inv;

    const int l0 = chunk * CHq;
    const float* xp = g_xv + ((size_t)b * Lq + l0) * Dq + k * Hq + h;
    const float* pp = g_pw + ((size_t)b * Lq + l0) * Kq + k;
    float* op = g_reim + (((size_t)b * Lq + l0) * Kq + k) * C2q + c;
    float* dp = g_den + ((size_t)b * Lq + l0) * Kq + k;

    float acc = 0.f, dacc = 0.f;
#pragma unroll 4
    for (int s = 0; s < CHq; ++s) {
        const float x = *xp;
        const float p = *pp;
        float sv, cv;
        __sincosf(x * th, &sv, &cv);
        const float poly = w0 + x * (w1 - w2 * x);
        const float v = poly * (isIm ? sv : cv);
        acc = fmaf(p, v, acc);
        dacc += p;
        *op = acc;
        if (c == 0) *dp = dacc;
        xp += Dq;
        pp += Kq;
        op += Kq * C2q;
        dp += Kq;
    }
    g_csum[(size_t)bid * C2q + c] = acc;
    if (c == 0) g_dsum[bid] = dacc;
}

// ---------------- pass 2: exclusive scan of chunk sums ----------------------
__global__ __launch_bounds__(256) void scan_fix()
{
    const int bk = blockIdx.x;
    const int c = threadIdx.x;
    float run = 0.f;
#pragma unroll 4
    for (int ch = 0; ch < NCH; ++ch) {
        const size_t idx = ((size_t)bk * NCH + ch) * C2q + c;
        const float t = g_csum[idx];
        g_csum[idx] = run;
        run += t;
    }
    if (c == 0) {
        float dr = 0.f;
        for (int ch = 0; ch < NCH; ++ch) {
            const int idx = bk * NCH + ch;
            const float t = g_dsum[idx];
            g_dsum[idx] = dr;
            dr += t;
        }
    }
}

// -------- RMS-norm + 256->32 projection + gate; fp16 yg tail ----------------
__global__ __launch_bounds__(256) void proj_kernel()
{
    __shared__ float sWn[C2q * Hq];          // 32 KB
    __shared__ float rowbuf[8][C2q];         // 8 KB

    for (int i = threadIdx.x; i < C2q * Hq; i += 256) sWn[i] = g_wn[i];
    __syncthreads();

    const int warp = threadIdx.x >> 5;
    const int lane = threadIdx.x & 31;
    const size_t row = (size_t)blockIdx.x * 8 + warp;   // < ROWSq exactly

    const size_t bl = row >> 5;              // K == 32
    const int k = (int)(row & 31);
    const int b = (int)(bl >> 11);           // L == 2048
    const int l = (int)(bl & (Lq - 1));
    const int chunk = l >> 5;                // CHq == 32
    const size_t obase = (((size_t)(b * Kq + k)) * NCH + chunk) * C2q;

    const float* rp = g_reim + row * C2q;
    const float* cp = g_csum + obase;
    float ss = 0.f;
#pragma unroll
    for (int j = 0; j < 8; ++j) {
        const float v = rp[lane + 32 * j] + cp[lane + 32 * j];
        ss = fmaf(v, v, ss);
        rowbuf[warp][lane + 32 * j] = v;
    }
#pragma unroll
    for (int o = 16; o; o >>= 1) ss += __shfl_xor_sync(0xFFFFFFFFu, ss, o);

    const float den = g_den[row] + g_dsum[(b * Kq + k) * NCH + chunk];
    const float invd = 1.f / fmaxf(den, 1e-4f);
    const float ms = ss * invd * invd * (1.f / (float)C2q);
    const float scale = invd * rsqrtf(ms + 1e-5f);
    __syncwarp();

    float acc = 0.f;
#pragma unroll 4
    for (int cc = 0; cc < C2q; ++cc)
        acc = fmaf(rowbuf[warp][cc], sWn[cc * Hq + lane], acc);

    const size_t oidx = bl * Dq + k * Hq + lane;
    const float val = acc * scale * g_gate[oidx];
    ((unsigned short*)g_yg)[oidx] = __half_as_ushort(__float2half_rn(val));
}

// ---------------- launch ----------------
extern "C" void kernel_launch(void* const* d_in, const int* in_sizes, int n_in,
                              void* d_out, int out_size)
{
    const float* x        = (const float*)d_in[0];
    const float* in_proj  = (const float*)d_in[1];
    const float* conv_w   = (const float*)d_in[2];
    const float* conv_b   = (const float*)d_in[3];
    const float* theta    = (const float*)d_in[4];
    const float* decay    = (const float*)d_in[5];
    const float* anchor   = (const float*)d_in[6];
    const float* sscale   = (const float*)d_in[7];
    const float* dlog     = (const float*)d_in[8];
    const float* nscale   = (const float*)d_in[9];
    const float* Wre      = (const float*)d_in[10];
    const float* Wim      = (const float*)d_in[11];
    const float* outw     = (const float*)d_in[12];
    float* out = (float*)d_out;

    cudaFuncSetAttribute(gemm_in, cudaFuncAttributeMaxDynamicSharedMemorySize,
                         GEMM_SMEM_BYTES);
    cudaFuncSetAttribute(gemm_out, cudaFuncAttributeMaxDynamicSharedMemorySize,
                         GEMM_SMEM_BYTES);

    // 0) pre-split operands (carved into dead scratch; R12-proven scheme)
    {
        const int nx = BLq * Dq;
        split_x_f16<<<(nx + 255) / 256, 256>>>(x, nx);
        const int n1 = Dq * TOTq;
        split_w_f16<<<(n1 + 255) / 256, 256>>>(in_proj, 1, n1);
    }
    // 1) z = x @ in_proj_w     (4096 x 2080 x 1024)  [fp16 asymmetric, 2 mma]
    {
        dim3 grid((TOTq + 127) / 128, BLq / 128);
        gemm_in<<<grid, 256, GEMM_SMEM_BYTES>>>();
    }
    // 2) depthwise causal conv + silu gate + p*time_weight
    {
        const long total = (long)BLq * TOTq;
        conv_kernel<<<(int)((total + 255) / 256), 256>>>(conv_w, conv_b, decay, anchor, sscale);
    }
    // 2.5) g_z now dead -> host w2 fp16 split there
    {
        const int n2 = Dq * Dq;
        split_w_f16<<<(n2 + 255) / 256, 256>>>(outw, 2, n2);
    }
    // 3) fold norm_scale into W
    prep_wn<<<(C2q * Hq + 255) / 256, 256>>>(nscale, Wre, Wim);
    // 4) chunked parallel cumsum (overwrites the x/w1 split regions — dead)
    scan_part<<<Bq * Kq * NCH, 256>>>(theta, dlog);
    scan_fix<<<Bq * Kq, 256>>>();
    // 5) RMS norm + head projection + gate -> fp16 yg (into g_yg)
    proj_kernel<<<ROWSq / 8, 256>>>();
    // 6) out = yg @ out_proj_w  (4096 x 1024 x 1024)  [fp16 asymmetric, 2 mma]
    {
        dim3 grid((Dq + 127) / 128, BLq / 128);
        gemm_out<<<grid, 256, GEMM_SMEM_BYTES>>>(out);
    }
}

// round 15
// speedup vs baseline: 1.4510x; 1.2840x over previous
#include <cuda_runtime.h>
#include <cuda_bf16.h>
#include <cuda_fp16.h>
#include <math.h>

// ---------------- problem constants ----------------
#define Bq   2
#define Lq   2048
#define Dq   1024
#define Kq   32
#define Mq   4
#define Aq   4
#define Hq   32          // D / K
#define CKq  4
#define TOTq (2 * Dq + Kq)   // 2080
#define BLq  (Bq * Lq)       // 4096
#define HMq  (Hq * Mq)       // 128
#define C2q  (2 * HMq)       // 256 channels (re + im)
#define ROWSq (BLq * Kq)     // 131072 (b,l,k) rows
#define NCH  64              // chunks along L
#define CHq  (Lq / NCH)      // 32 steps per chunk

// ------------- scratch: EXACTLY the R7/R12/R14 (passing) static set ---------
__device__ float g_z[(size_t)BLq * TOTq];          // in_proj output; later hosts w2 fp16
__device__ float g_xv[(size_t)BLq * Dq];           // x_val (post conv)
__device__ float g_gate[(size_t)BLq * Dq];         // silu gate
__device__ float g_pw[(size_t)BLq * Kq];           // p * time_weight
__device__ float g_reim[(size_t)ROWSq * C2q];      // scan prefixes; hosts x/w1 fp16 pre-scan
__device__ float g_den[(size_t)ROWSq];
__device__ float g_csum[(size_t)Bq * Kq * NCH * C2q];
__device__ float g_dsum[(size_t)Bq * Kq * NCH];
__device__ float g_wn[C2q * Hq];                   // norm_scale-folded [W_re;W_im]
__device__ float g_yg[(size_t)BLq * Dq];           // hosts yg fp16

// ================= helpers =================
__device__ __forceinline__ unsigned smem_addr_u32(const void* p) {
    unsigned a;
    asm("{ .reg .u64 t; cvta.to.shared.u64 t, %1; cvt.u32.u64 %0, t; }"
        : "=r"(a) : "l"(p));
    return a;
}
__device__ __forceinline__ void ldmat4(unsigned& r0, unsigned& r1,
                                       unsigned& r2, unsigned& r3, unsigned a) {
    asm volatile("ldmatrix.sync.aligned.m8n8.x4.shared.b16 {%0,%1,%2,%3}, [%4];"
        : "=r"(r0), "=r"(r1), "=r"(r2), "=r"(r3) : "r"(a));
}
__device__ __forceinline__ void ldmat4t(unsigned& r0, unsigned& r1,
                                        unsigned& r2, unsigned& r3, unsigned a) {
    asm volatile("ldmatrix.sync.aligned.m8n8.x4.trans.shared.b16 {%0,%1,%2,%3}, [%4];"
        : "=r"(r0), "=r"(r1), "=r"(r2), "=r"(r3) : "r"(a));
}
__device__ __forceinline__ void mmaf16(float* d, const unsigned* a, const unsigned* b) {
    asm volatile(
        "mma.sync.aligned.m16n8k16.row.col.f32.f16.f16.f32 "
        "{%0,%1,%2,%3}, {%4,%5,%6,%7}, {%8,%9}, {%0,%1,%2,%3};"
        : "+f"(d[0]), "+f"(d[1]), "+f"(d[2]), "+f"(d[3])
        : "r"(a[0]), "r"(a[1]), "r"(a[2]), "r"(a[3]), "r"(b[0]), "r"(b[1]));
}

// ------------- fp32 -> fp16 casts (pure scalar, no locals addressed) --------
__global__ void split_x_f16(const float* __restrict__ src, int n)
{
    const int i = blockIdx.x * blockDim.x + threadIdx.x;
    if (i >= n) return;
    ((unsigned short*)g_reim)[i] = __half_as_ushort(__float2half_rn(src[i]));
}
__global__ void split_w_f16(const float* __restrict__ src, int which, int n)
{
    const int i = blockIdx.x * blockDim.x + threadIdx.x;
    if (i >= n) return;
    unsigned short* hi = (which == 1)
        ? (unsigned short*)g_reim + (size_t)BLq * Dq
        : (unsigned short*)g_z;
    hi[i] = __half_as_ushort(__float2half_rn(src[i]));
}

// ========== fp16 tensor-core GEMM: C = A * B, 1 mma per k16 ================
// R14-proven skeleton: 128x128x32 block, 8 warps, double-buffered SMEM,
// register prefetch, fp32 accumulate.
#define APADg 40     // A k-stride in fp16 elems (80B row, ldmatrix conflict-free)
#define BPADg 136    // B n-stride in fp16 elems (272B row)
#define OAg  0
#define OBg (128 * APADg)                 // 5120
#define STg (OBg + 32 * BPADg)            // 9472 elems per stage
#define GEMM_SMEM_BYTES (2 * STg * 2)     // 37888 bytes

__device__ __forceinline__ void hgemm_body(
    const unsigned short* __restrict__ Ah,
    const unsigned short* __restrict__ Bh,
    float* __restrict__ C, int Nc, int Kd)
{
    extern __shared__ __align__(16) unsigned short sm[];
    const unsigned sbase = smem_addr_u32(sm);

    const int tid  = threadIdx.x;
    const int lane = tid & 31;
    const int warp = tid >> 5;
    const int wm = (warp >> 2) * 64;
    const int wn = (warp & 3) * 32;
    const int bm0 = blockIdx.y * 128;
    const int bn0 = blockIdx.x * 128;

    float acc[4][4][4];
#pragma unroll
    for (int i = 0; i < 4; ++i)
#pragma unroll
        for (int j = 0; j < 4; ++j)
#pragma unroll
            for (int r = 0; r < 4; ++r) acc[i][j][r] = 0.f;

    int aRow[4], aC4[4], bRow[4], bC4[4];
#pragma unroll
    for (int i = 0; i < 4; ++i) {
        const int lin = i * 256 + tid;
        aRow[i] = lin >> 3;  aC4[i] = (lin & 7) * 4;
        bRow[i] = lin >> 5;  bC4[i] = (lin & 31) * 4;
    }

    const int nKT = Kd >> 5;
    uint2 ha[4], hb[4];
    const uint2 z2 = make_uint2(0u, 0u);

    // preload tile 0
#pragma unroll
    for (int i = 0; i < 4; ++i) {
        ha[i] = *reinterpret_cast<const uint2*>(Ah + (size_t)(bm0 + aRow[i]) * Kd + aC4[i]);
        const int gbc = bn0 + bC4[i];
        hb[i] = z2;
        if (gbc < Nc)   // Nc % 4 == 0 -> whole-chunk predicate
            hb[i] = *reinterpret_cast<const uint2*>(Bh + (size_t)bRow[i] * Nc + gbc);
    }
#pragma unroll
    for (int i = 0; i < 4; ++i) {
        *reinterpret_cast<uint2*>(&sm[OAg + aRow[i] * APADg + aC4[i]]) = ha[i];
        *reinterpret_cast<uint2*>(&sm[OBg + bRow[i] * BPADg + bC4[i]]) = hb[i];
    }
    __syncthreads();

    int st = 0;
    for (int kt = 0; kt < nKT; ++kt) {
        const bool more = (kt + 1 < nKT);
        if (more) {
            const int k0 = (kt + 1) * 32;
#pragma unroll
            for (int i = 0; i < 4; ++i) {
                ha[i] = *reinterpret_cast<const uint2*>(
                    Ah + (size_t)(bm0 + aRow[i]) * Kd + k0 + aC4[i]);
                const int gbc = bn0 + bC4[i];
                hb[i] = z2;
                if (gbc < Nc)
                    hb[i] = *reinterpret_cast<const uint2*>(
                        Bh + (size_t)(k0 + bRow[i]) * Nc + gbc);
            }
        }

#pragma unroll
        for (int kk = 0; kk < 32; kk += 16) {
            unsigned af[4][4];
            const int arowL = (lane & 7) + ((lane >> 3) & 1) * 8;
            const int acolL = kk + (lane >> 4) * 8;
#pragma unroll
            for (int i = 0; i < 4; ++i) {
                const unsigned ad = sbase +
                    (unsigned)(st + OAg + (wm + i * 16 + arowL) * APADg + acolL) * 2u;
                ldmat4(af[i][0], af[i][1], af[i][2], af[i][3], ad);
            }
            unsigned bf[4][2];
            const int krow = kk + (lane & 7) + ((lane >> 3) & 1) * 8;
#pragma unroll
            for (int jj = 0; jj < 32; jj += 16) {
                const int ncol = wn + jj + (lane >> 4) * 8;
                const unsigned bd = sbase +
                    (unsigned)(st + OBg + krow * BPADg + ncol) * 2u;
                unsigned r0, r1, r2, r3;
                ldmat4t(r0, r1, r2, r3, bd);
                bf[jj / 8 + 0][0] = r0; bf[jj / 8 + 0][1] = r1;
                bf[jj / 8 + 1][0] = r2; bf[jj / 8 + 1][1] = r3;
            }
#pragma unroll
            for (int i = 0; i < 4; ++i)
#pragma unroll
                for (int j = 0; j < 4; ++j)
                    mmaf16(acc[i][j], af[i], bf[j]);
        }

        if (more) {
            const int ns = st ^ STg;
#pragma unroll
            for (int i = 0; i < 4; ++i) {
                *reinterpret_cast<uint2*>(&sm[ns + OAg + aRow[i] * APADg + aC4[i]]) = ha[i];
                *reinterpret_cast<uint2*>(&sm[ns + OBg + bRow[i] * BPADg + bC4[i]]) = hb[i];
            }
            __syncthreads();
            st = ns;
        }
    }

    const int g = lane >> 2;
    const int t2 = (lane & 3) * 2;
#pragma unroll
    for (int i = 0; i < 4; ++i) {
        const int row = bm0 + wm + i * 16 + g;
#pragma unroll
        for (int j = 0; j < 4; ++j) {
            const int col = bn0 + wn + j * 8 + t2;
            if (col < Nc) {
                *reinterpret_cast<float2*>(&C[(size_t)row * Nc + col]) =
                    make_float2(acc[i][j][0], acc[i][j][1]);
                *reinterpret_cast<float2*>(&C[(size_t)(row + 8) * Nc + col]) =
                    make_float2(acc[i][j][2], acc[i][j][3]);
            }
        }
    }
}

__global__ __launch_bounds__(256) void gemm_in()
{
    const unsigned short* xh  = (const unsigned short*)g_reim;
    const unsigned short* w1h = xh + (size_t)BLq * Dq;
    hgemm_body(xh, w1h, g_z, TOTq, Dq);
}

__global__ __launch_bounds__(256) void gemm_out(float* __restrict__ out)
{
    const unsigned short* ygh = (const unsigned short*)g_yg;
    const unsigned short* w2h = (const unsigned short*)g_z;
    hgemm_body(ygh, w2h, out, Dq, Dq);
}

// --------- depthwise causal conv + pointwise classify (2D grid, no div) -----
__global__ void conv_kernel(
    const float* __restrict__ cw, const float* __restrict__ cb,
    const float* __restrict__ dslopes, const float* __restrict__ aslopes,
    const float* __restrict__ sscale)
{
    const int c = blockIdx.x * blockDim.x + threadIdx.x;
    if (c >= TOTq) return;
    const size_t bl = blockIdx.y;            // 0..BLq-1
    const int l = (int)(bl & (Lq - 1));

    float acc = cb[c];
#pragma unroll
    for (int j = 0; j < CKq; ++j) {
        const int ls = l + j - (CKq - 1);
        if (ls >= 0)
            acc = fmaf(g_z[(bl - l + ls) * TOTq + c], cw[j * TOTq + c], acc);
    }

    if (c < Dq) {
        g_xv[bl * Dq + c] = acc;
    } else if (c < 2 * Dq) {
        g_gate[bl * Dq + (c - Dq)] = acc / (1.f + __expf(-acc));
    } else {
        const int k = c - 2 * Dq;
        float s = sscale[k] * acc;
        s = fminf(fmaxf(s, -20.f), 20.f);
        const float p = __expf(s);
        float sl, tw;
        if (k < Kq - Aq) {
            sl = log1pf(expf(dslopes[k]));                 // softplus
            tw = __expf(-sl * (float)(Lq - 1 - l));
        } else {
            sl = log1pf(expf(aslopes[k - (Kq - Aq)]));
            tw = __expf(-sl * (float)l);
        }
        g_pw[bl * Kq + k] = p * tw;
    }
}

// ---------------- fold norm_scale into [W_re; W_im] ----------------
__global__ void prep_wn(const float* __restrict__ ns,
                        const float* __restrict__ Wre,
                        const float* __restrict__ Wim)
{
    const int i = blockIdx.x * blockDim.x + threadIdx.x;
    if (i >= C2q * Hq) return;
    const int c = i / Hq, hh = i % Hq;
    const float w = (c < HMq) ? Wre[c * Hq + hh] : Wim[(c - HMq) * Hq + hh];
    g_wn[i] = ns[c] * w;
}

// ---- pass 1: per-chunk compute + local cumsum (128 thr; shared sincos) -----
__global__ __launch_bounds__(128) void scan_part(
    const float* __restrict__ theta, const float* __restrict__ dlog)
{
    const int bid   = blockIdx.x;            // bk * NCH + chunk
    const int bk    = bid >> 6;              // NCH == 64
    const int chunk = bid & (NCH - 1);
    const int b = bk >> 5, k = bk & (Kq - 1);
    const int c = threadIdx.x;               // 0..127 -> (h,m)
    const int h = c >> 2;
    const int m = c & (Mq - 1);

    const float th = theta[(k * Hq + h) * Mq + m];

    const float d0 = dlog[0], d1 = dlog[1], d2 = dlog[2];
    const float mx = fmaxf(d0, fmaxf(d1, d2));
    const float e0 = __expf(d0 - mx), e1 = __expf(d1 - mx), e2 = __expf(d2 - mx);
    const float inv = 1.f / (e0 + e1 + e2);
    const float w0 = e0 * inv, w1 = e1 * inv, w2 = e2 * inv;

    const int l0 = chunk * CHq;
    const float* xp = g_xv + ((size_t)b * Lq + l0) * Dq + k * Hq + h;
    const float* pp = g_pw + ((size_t)b * Lq + l0) * Kq + k;
    float* op = g_reim + (((size_t)b * Lq + l0) * Kq + k) * C2q + c;
    float* dp = g_den + ((size_t)b * Lq + l0) * Kq + k;

    float accR = 0.f, accI = 0.f, dacc = 0.f;
#pragma unroll 4
    for (int s = 0; s < CHq; ++s) {
        const float x = *xp;
        const float p = *pp;
        float sv, cv;
        __sincosf(x * th, &sv, &cv);
        const float poly = w0 + x * (w1 - w2 * x);
        accR = fmaf(p, poly * cv, accR);
        accI = fmaf(p, poly * sv, accI);
        dacc += p;
        op[0]   = accR;
        op[HMq] = accI;
        if (c == 0) *dp = dacc;
        xp += Dq;
        pp += Kq;
        op += Kq * C2q;
        dp += Kq;
    }
    g_csum[(size_t)bid * C2q + c]       = accR;
    g_csum[(size_t)bid * C2q + c + HMq] = accI;
    if (c == 0) g_dsum[bid] = dacc;
}

// ---------------- pass 2: exclusive scan of chunk sums ----------------------
__global__ __launch_bounds__(256) void scan_fix()
{
    const int bk = blockIdx.x;
    const int c = threadIdx.x;
    float run = 0.f;
#pragma unroll 4
    for (int ch = 0; ch < NCH; ++ch) {
        const size_t idx = ((size_t)bk * NCH + ch) * C2q + c;
        const float t = g_csum[idx];
        g_csum[idx] = run;
        run += t;
    }
    if (c == 0) {
        float dr = 0.f;
        for (int ch = 0; ch < NCH; ++ch) {
            const int idx = bk * NCH + ch;
            const float t = g_dsum[idx];
            g_dsum[idx] = dr;
            dr += t;
        }
    }
}

// -------- RMS-norm + 256->32 projection + gate; fp16 yg tail ----------------
__global__ __launch_bounds__(256) void proj_kernel()
{
    __shared__ float sWn[C2q * Hq];          // 32 KB
    __shared__ float rowbuf[8][C2q];         // 8 KB

    for (int i = threadIdx.x; i < C2q * Hq; i += 256) sWn[i] = g_wn[i];
    __syncthreads();

    const int warp = threadIdx.x >> 5;
    const int lane = threadIdx.x & 31;
    const size_t row = (size_t)blockIdx.x * 8 + warp;   // < ROWSq exactly

    const size_t bl = row >> 5;              // K == 32
    const int k = (int)(row & 31);
    const int b = (int)(bl >> 11);           // L == 2048
    const int l = (int)(bl & (Lq - 1));
    const int chunk = l >> 5;                // CHq == 32
    const size_t obase = (((size_t)(b * Kq + k)) * NCH + chunk) * C2q;

    const float* rp = g_reim + row * C2q;
    const float* cp = g_csum + obase;
    float ss = 0.f;
#pragma unroll
    for (int j = 0; j < 8; ++j) {
        const float v = rp[lane + 32 * j] + cp[lane + 32 * j];
        ss = fmaf(v, v, ss);
        rowbuf[warp][lane + 32 * j] = v;
    }
#pragma unroll
    for (int o = 16; o; o >>= 1) ss += __shfl_xor_sync(0xFFFFFFFFu, ss, o);

    const float den = g_den[row] + g_dsum[(b * Kq + k) * NCH + chunk];
    const float invd = 1.f / fmaxf(den, 1e-4f);
    const float ms = ss * invd * invd * (1.f / (float)C2q);
    const float scale = invd * rsqrtf(ms + 1e-5f);
    __syncwarp();

    float acc = 0.f;
#pragma unroll 4
    for (int cc = 0; cc < C2q; ++cc)
        acc = fmaf(rowbuf[warp][cc], sWn[cc * Hq + lane], acc);

    const size_t oidx = bl * Dq + k * Hq + lane;
    const float val = acc * scale * g_gate[oidx];
    ((unsigned short*)g_yg)[oidx] = __half_as_ushort(__float2half_rn(val));
}

// ---------------- launch ----------------
extern "C" void kernel_launch(void* const* d_in, const int* in_sizes, int n_in,
                              void* d_out, int out_size)
{
    const float* x        = (const float*)d_in[0];
    const float* in_proj  = (const float*)d_in[1];
    const float* conv_w   = (const float*)d_in[2];
    const float* conv_b   = (const float*)d_in[3];
    const float* theta    = (const float*)d_in[4];
    const float* decay    = (const float*)d_in[5];
    const float* anchor   = (const float*)d_in[6];
    const float* sscale   = (const float*)d_in[7];
    const float* dlog     = (const float*)d_in[8];
    const float* nscale   = (const float*)d_in[9];
    const float* Wre      = (const float*)d_in[10];
    const float* Wim      = (const float*)d_in[11];
    const float* outw     = (const float*)d_in[12];
    float* out = (float*)d_out;

    cudaFuncSetAttribute(gemm_in, cudaFuncAttributeMaxDynamicSharedMemorySize,
                         GEMM_SMEM_BYTES);
    cudaFuncSetAttribute(gemm_out, cudaFuncAttributeMaxDynamicSharedMemorySize,
                         GEMM_SMEM_BYTES);

    // 0) cast operands to fp16 (carved into dead scratch; R12/R14-proven)
    {
        const int nx = BLq * Dq;
        split_x_f16<<<(nx + 255) / 256, 256>>>(x, nx);
        const int n1 = Dq * TOTq;
        split_w_f16<<<(n1 + 255) / 256, 256>>>(in_proj, 1, n1);
    }
    // 1) z = x @ in_proj_w     (4096 x 2080 x 1024)  [fp16, 1 mma/k16]
    {
        dim3 grid((TOTq + 127) / 128, BLq / 128);
        gemm_in<<<grid, 256, GEMM_SMEM_BYTES>>>();
    }
    // 2) depthwise causal conv + silu gate + p*time_weight (2D grid)
    {
        dim3 grid((TOTq + 255) / 256, BLq);
        conv_kernel<<<grid, 256>>>(conv_w, conv_b, decay, anchor, sscale);
    }
    // 2.5) g_z now dead -> host w2 fp16 there
    {
        const int n2 = Dq * Dq;
        split_w_f16<<<(n2 + 255) / 256, 256>>>(outw, 2, n2);
    }
    // 3) fold norm_scale into W
    prep_wn<<<(C2q * Hq + 255) / 256, 256>>>(nscale, Wre, Wim);
    // 4) chunked parallel cumsum (128 thr/block, shared sincos)
    scan_part<<<Bq * Kq * NCH, 128>>>(theta, dlog);
    scan_fix<<<Bq * Kq, 256>>>();
    // 5) RMS norm + head projection + gate -> fp16 yg (into g_yg)
    proj_kernel<<<ROWSq / 8, 256>>>();
    // 6) out = yg @ out_proj_w  (4096 x 1024 x 1024)  [fp16, 1 mma/k16]
    {
        dim3 grid((Dq + 127) / 128, BLq / 128);
        gemm_out<<<grid, 256, GEMM_SMEM_BYTES>>>(out);
    }
}